// round 1
// baseline (speedup 1.0000x reference)
#include <cuda_runtime.h>
#include <math_constants.h>

#define WSZ    8
#define P2     64
#define CH     128
#define W1G    32          // windows per side
#define NWPB   1024        // windows per batch image
#define BATCH  8
#define NWIN   (BATCH*NWPB) // 8192
#define HD     32
#define NH     4
#define SHIFT  4
#define STR    129         // padded smem row stride (floats)

// ---------------- scratch (device globals; no runtime alloc) ----------------
__device__ float g_xw [(size_t)NWIN * P2 * CH]; // shifted+windowed x, [win][tok][ch]
__device__ float g_off[NWIN * P2 * 2];          // per-token intra offsets
__device__ float g_oi [NWIN * 2];               // per-window inter offset

// ---------------- kernel 1: window gather + offset MLPs ----------------
__global__ __launch_bounds__(256)
void k_prep(const float* __restrict__ x,
            const float* __restrict__ wi_w, const float* __restrict__ wi_b,
            const float* __restrict__ w1_w, const float* __restrict__ w1_b,
            const float* __restrict__ w2_w, const float* __restrict__ w2_b)
{
    __shared__ float sT[P2 * STR];
    __shared__ float sT1[P2 * 2];

    const int win = blockIdx.x;
    const int b   = win >> 10;
    const int wr  = win & 1023;
    const int wi  = wr >> 5;
    const int wj  = wr & 31;
    const int tid = threadIdx.x;

    float* gx = g_xw + (size_t)win * P2 * CH;

    // gather shifted window (roll by -SHIFT => src = idx + SHIFT mod 256)
    for (int idx = tid; idx < P2 * CH; idx += 256) {
        const int tok = idx >> 7, ch = idx & 127;
        const int pi = tok >> 3, pj = tok & 7;
        const int r = (wi * 8 + pi + SHIFT) & 255;
        const int c = (wj * 8 + pj + SHIFT) & 255;
        const float v = x[(size_t)((((b << 8) + r) << 8) + c) * CH + ch];
        sT[tok * STR + ch] = v;
        gx[idx] = v;
    }
    __syncthreads();

    // 256 jobs: (kind, tok, d) -> 128-dot
    {
        const int kind = tid >> 7;          // 0: wi_w -> off_intra, 1: w1_w -> t1
        const int rem  = tid & 127;
        const int tok  = rem >> 1;
        const int d    = rem & 1;
        const float* w = kind ? w1_w : wi_w;
        float acc = 0.f;
        #pragma unroll 8
        for (int ch = 0; ch < 128; ++ch)
            acc = fmaf(sT[tok * STR + ch], w[ch * 2 + d], acc);
        if (kind) sT1[tok * 2 + d] = acc + w1_b[d];
        else      g_off[win * 128 + tok * 2 + d] = acc + wi_b[d];
    }
    __syncthreads();

    if (tid < 2) {  // oi[e] = w2_b[e] + sum_f t1[f] * w2_w[f][e]
        float acc = w2_b[tid];
        for (int f = 0; f < 128; ++f)
            acc = fmaf(sT1[f], w2_w[f * 2 + tid], acc);
        g_oi[win * 2 + tid] = acc;
    }
}

// 64x128 GEMM: out_s[tok][co] = in_s[tok][:] @ w[:, woff+co] + bias[boff+co]
__device__ __forceinline__
void gemm_block(const float* __restrict__ in_s, const float* __restrict__ w,
                int wstride, int woff, const float* __restrict__ bias, int boff,
                float* __restrict__ out_s, int ty, int tx)
{
    float acc[8][4] = {};
    #pragma unroll 2
    for (int ci = 0; ci < 128; ++ci) {
        const float* wr = w + (size_t)ci * wstride + woff + tx;
        const float w0 = wr[0], w1 = wr[32], w2 = wr[64], w3 = wr[96];
        const float* ar = in_s + (ty * 8) * STR + ci;
        #pragma unroll
        for (int r = 0; r < 8; ++r) {
            const float a = ar[r * STR];
            acc[r][0] = fmaf(a, w0, acc[r][0]);
            acc[r][1] = fmaf(a, w1, acc[r][1]);
            acc[r][2] = fmaf(a, w2, acc[r][2]);
            acc[r][3] = fmaf(a, w3, acc[r][3]);
        }
    }
    #pragma unroll
    for (int r = 0; r < 8; ++r)
        #pragma unroll
        for (int u = 0; u < 4; ++u)
            out_s[(ty * 8 + r) * STR + tx + 32 * u] = acc[r][u] + bias[boff + tx + 32 * u];
}

// ---------------- kernel 2: sampling + attention + o-proj, fused per window ----
__global__ __launch_bounds__(256)
void k_main(const float* __restrict__ rpp,
            const float* __restrict__ q_w,  const float* __restrict__ q_b,
            const float* __restrict__ kv_w, const float* __restrict__ kv_b,
            const float* __restrict__ o_w,  const float* __restrict__ o_b,
            float* __restrict__ out)
{
    extern __shared__ float sm[];
    float* sA   = sm;                   // xd -> xw -> k
    float* sB   = sA + P2 * STR;        // xd2 -> attn-out
    float* sC   = sB + P2 * STR;        // q
    float* sD   = sC + P2 * STR;        // v
    float* sSim = sD + P2 * STR;        // 64x64
    float* sW   = sSim + 4096;          // 64x4 intra weights
    int*   sIdx = (int*)(sW + 256);     // 64x4 intra indices

    const int win = blockIdx.x;
    const int b   = win >> 10;
    const int wr  = win & 1023;
    const int wi  = wr >> 5;
    const int wj  = wr & 31;
    const int tid = threadIdx.x;
    const int ty  = tid >> 5, tx = tid & 31;

    // ---- inter-window bilinear blend -> sA (xd) ----
    {
        const float ox = g_oi[win * 2 + 0], oy = g_oi[win * 2 + 1];
        const float gxp = (float)wj + ox, gyp = (float)wi + oy;
        const float x0f = floorf(gxp), y0f = floorf(gyp);
        const float fx = gxp - x0f, fy = gyp - y0f;
        const int x0 = (int)x0f, y0 = (int)y0f;
        const float wgt[4] = {(1.f - fx) * (1.f - fy), fx * (1.f - fy),
                              (1.f - fx) * fy,          fx * fy};
        const float* nb[4];
        float nww[4];
        #pragma unroll
        for (int k = 0; k < 4; ++k) {
            const int xx = x0 + (k & 1), yy = y0 + (k >> 1);
            const bool valid = (xx >= 0) && (xx < W1G) && (yy >= 0) && (yy < W1G);
            nb[k]  = valid ? (g_xw + (size_t)((b << 10) + (yy << 5) + xx) * P2 * CH) : g_xw;
            nww[k] = valid ? wgt[k] : 0.f;
        }
        for (int idx = tid; idx < P2 * CH; idx += 256) {
            const float acc = nww[0] * nb[0][idx] + nww[1] * nb[1][idx]
                            + nww[2] * nb[2][idx] + nww[3] * nb[3][idx];
            sA[(idx >> 7) * STR + (idx & 127)] = acc;
        }
    }
    // ---- intra sample indices/weights (per token) ----
    if (tid < 64) {
        const int tok = tid, pi = tok >> 3, pj = tok & 7;
        const float o0 = g_off[win * 128 + tok * 2], o1 = g_off[win * 128 + tok * 2 + 1];
        const float gx2 = (float)pj + o0, gy2 = (float)pi + o1;
        const float xf = floorf(gx2), yf = floorf(gy2);
        const float fx = gx2 - xf, fy = gy2 - yf;
        const int x0 = (int)xf, y0 = (int)yf;
        const float ww[4] = {(1.f - fx) * (1.f - fy), fx * (1.f - fy),
                             (1.f - fx) * fy,          fx * fy};
        #pragma unroll
        for (int k = 0; k < 4; ++k) {
            const int xx = x0 + (k & 1), yy = y0 + (k >> 1);
            const bool valid = (xx >= 0) && (xx < WSZ) && (yy >= 0) && (yy < WSZ);
            sIdx[tok * 4 + k] = valid ? (yy * 8 + xx) : 0;
            sW[tok * 4 + k]   = valid ? ww[k] : 0.f;
        }
    }
    __syncthreads();

    // ---- intra-window gather -> sB (xd2) ----
    for (int idx = tid; idx < P2 * CH; idx += 256) {
        const int tok = idx >> 7, ch = idx & 127;
        float acc = 0.f;
        #pragma unroll
        for (int k = 0; k < 4; ++k)
            acc = fmaf(sW[tok * 4 + k], sA[sIdx[tok * 4 + k] * STR + ch], acc);
        sB[tok * STR + ch] = acc;
    }
    __syncthreads();

    // ---- own window xw -> sA ----
    {
        const float* gx = g_xw + (size_t)win * P2 * CH;
        for (int idx = tid; idx < P2 * CH; idx += 256)
            sA[(idx >> 7) * STR + (idx & 127)] = gx[idx];
    }
    __syncthreads();

    // ---- q = xw @ q_w -> sC ----
    gemm_block(sA, q_w, 128, 0, q_b, 0, sC, ty, tx);
    __syncthreads();
    // ---- k = xd2 @ kv_w[:, :128] -> sA ; v = xd2 @ kv_w[:, 128:] -> sD ----
    gemm_block(sB, kv_w, 256, 0,   kv_b, 0,   sA, ty, tx);
    gemm_block(sB, kv_w, 256, 128, kv_b, 128, sD, ty, tx);
    __syncthreads();

    // ---- attention (warp owns its 8 query rows end-to-end) ----
    const float scale = 0.17677669529663687f; // 1/sqrt(32)
    const bool lastRow = (wi == W1G - 1), lastCol = (wj == W1G - 1);
    for (int hh = 0; hh < NH; ++hh) {
        float acc[8][2] = {};
        const float* qb_ = sC + (ty * 8) * STR + hh * HD;
        const float* k0p = sA + tx * STR + hh * HD;
        const float* k1p = sA + (tx + 32) * STR + hh * HD;
        #pragma unroll 4
        for (int d = 0; d < HD; ++d) {
            const float kk0 = k0p[d], kk1 = k1p[d];
            #pragma unroll
            for (int r = 0; r < 8; ++r) {
                const float qv = qb_[r * STR + d];
                acc[r][0] = fmaf(qv, kk0, acc[r][0]);
                acc[r][1] = fmaf(qv, kk1, acc[r][1]);
            }
        }
        const float* rb = rpp + hh * 225;
        #pragma unroll
        for (int r = 0; r < 8; ++r) {
            const int i = ty * 8 + r, pi_i = i >> 3, pj_i = i & 7;
            #pragma unroll
            for (int u = 0; u < 2; ++u) {
                const int j = tx + 32 * u, pi_j = j >> 3, pj_j = j & 7;
                const float bias = rb[(pi_i - pi_j + 7) * 15 + (pj_i - pj_j + 7)];
                const bool msk = (lastRow && ((pi_i < 4) != (pi_j < 4)))
                              || (lastCol && ((pj_i < 4) != (pj_j < 4)));
                sSim[i * 64 + j] = msk ? -CUDART_INF_F : fmaf(acc[r][u], scale, bias);
            }
        }
        __syncwarp();
        // softmax
        #pragma unroll
        for (int r = 0; r < 8; ++r) {
            const int i = ty * 8 + r;
            const float a = sSim[i * 64 + tx], bb = sSim[i * 64 + tx + 32];
            float m = fmaxf(a, bb);
            #pragma unroll
            for (int s2 = 16; s2 > 0; s2 >>= 1) m = fmaxf(m, __shfl_xor_sync(0xffffffffu, m, s2));
            const float e0 = __expf(a - m), e1 = __expf(bb - m);
            float s = e0 + e1;
            #pragma unroll
            for (int s2 = 16; s2 > 0; s2 >>= 1) s += __shfl_xor_sync(0xffffffffu, s, s2);
            const float inv = 1.f / s;
            sSim[i * 64 + tx]      = e0 * inv;
            sSim[i * 64 + tx + 32] = e1 * inv;
        }
        __syncwarp();
        // probs @ v -> attn-out slice (head channels disjoint, into sB)
        float po[8] = {};
        #pragma unroll 4
        for (int j = 0; j < 64; ++j) {
            const float vv = sD[j * STR + hh * HD + tx];
            #pragma unroll
            for (int r = 0; r < 8; ++r)
                po[r] = fmaf(sSim[(ty * 8 + r) * 64 + j], vv, po[r]);
        }
        #pragma unroll
        for (int r = 0; r < 8; ++r)
            sB[(ty * 8 + r) * STR + hh * HD + tx] = po[r];
        __syncwarp();
    }
    __syncthreads();

    // ---- o projection + un-shift scatter ----
    {
        float acc[8][4] = {};
        #pragma unroll 2
        for (int ci = 0; ci < 128; ++ci) {
            const float* wrp = o_w + ci * 128 + tx;
            const float w0 = wrp[0], w1 = wrp[32], w2 = wrp[64], w3 = wrp[96];
            #pragma unroll
            for (int r = 0; r < 8; ++r) {
                const float a = sB[(ty * 8 + r) * STR + ci];
                acc[r][0] = fmaf(a, w0, acc[r][0]);
                acc[r][1] = fmaf(a, w1, acc[r][1]);
                acc[r][2] = fmaf(a, w2, acc[r][2]);
                acc[r][3] = fmaf(a, w3, acc[r][3]);
            }
        }
        #pragma unroll
        for (int r = 0; r < 8; ++r) {
            const int tok = ty * 8 + r, pi = tok >> 3, pj = tok & 7;
            const int rr = (wi * 8 + pi + SHIFT) & 255;
            const int cc = (wj * 8 + pj + SHIFT) & 255;
            float* op = out + (size_t)((((b << 8) + rr) << 8) + cc) * CH;
            #pragma unroll
            for (int u = 0; u < 4; ++u)
                op[tx + 32 * u] = acc[r][u] + o_b[tx + 32 * u];
        }
    }
}

extern "C" void kernel_launch(void* const* d_in, const int* in_sizes, int n_in,
                              void* d_out, int out_size)
{
    const float* x    = (const float*)d_in[0];
    const float* rpp  = (const float*)d_in[1];
    const float* wi_w = (const float*)d_in[2];
    const float* wi_b = (const float*)d_in[3];
    const float* w1_w = (const float*)d_in[4];
    const float* w1_b = (const float*)d_in[5];
    const float* w2_w = (const float*)d_in[6];
    const float* w2_b = (const float*)d_in[7];
    const float* q_w  = (const float*)d_in[8];
    const float* q_b  = (const float*)d_in[9];
    const float* kv_w = (const float*)d_in[10];
    const float* kv_b = (const float*)d_in[11];
    const float* o_w  = (const float*)d_in[12];
    const float* o_b  = (const float*)d_in[13];
    float* out = (float*)d_out;

    const size_t smem2 = (size_t)(4 * P2 * STR + 4096 + 256 + 256) * sizeof(float);
    cudaFuncSetAttribute(k_main, cudaFuncAttributeMaxDynamicSharedMemorySize, (int)smem2);

    k_prep<<<NWIN, 256>>>(x, wi_w, wi_b, w1_w, w1_b, w2_w, w2_b);
    k_main<<<NWIN, 256, smem2>>>(rpp, q_w, q_b, kv_w, kv_b, o_w, o_b, out);
}

// round 2
// speedup vs baseline: 1.1932x; 1.1932x over previous
#include <cuda_runtime.h>
#include <math_constants.h>

#define WSZ    8
#define P2     64
#define CH     128
#define W1G    32
#define NWPB   1024
#define BATCH  8
#define NWIN   (BATCH*NWPB)
#define HD     32
#define NH     4
#define SHIFT  4
#define STR    129
#define NTHR   512

// ---------------- scratch ----------------
__device__ float g_xw [(size_t)NWIN * P2 * CH];
__device__ float g_off[NWIN * P2 * 2];
__device__ float g_oi [NWIN * 2];

// ---------------- kernel 1: window gather + offset MLPs ----------------
__global__ __launch_bounds__(256)
void k_prep(const float* __restrict__ x,
            const float* __restrict__ wi_w, const float* __restrict__ wi_b,
            const float* __restrict__ w1_w, const float* __restrict__ w1_b,
            const float* __restrict__ w2_w, const float* __restrict__ w2_b)
{
    __shared__ float sT[P2 * STR];
    __shared__ float sT1[P2 * 2];

    const int win = blockIdx.x;
    const int b   = win >> 10;
    const int wr  = win & 1023;
    const int wi  = wr >> 5;
    const int wj  = wr & 31;
    const int tid = threadIdx.x;

    float* gx = g_xw + (size_t)win * P2 * CH;

    for (int idx = tid; idx < P2 * CH; idx += 256) {
        const int tok = idx >> 7, ch = idx & 127;
        const int pi = tok >> 3, pj = tok & 7;
        const int r = (wi * 8 + pi + SHIFT) & 255;
        const int c = (wj * 8 + pj + SHIFT) & 255;
        const float v = x[(size_t)((((b << 8) + r) << 8) + c) * CH + ch];
        sT[tok * STR + ch] = v;
        gx[idx] = v;
    }
    __syncthreads();

    {
        const int kind = tid >> 7;
        const int rem  = tid & 127;
        const int tok  = rem >> 1;
        const int d    = rem & 1;
        const float* w = kind ? w1_w : wi_w;
        float acc = 0.f;
        #pragma unroll 8
        for (int ch = 0; ch < 128; ++ch)
            acc = fmaf(sT[tok * STR + ch], w[ch * 2 + d], acc);
        if (kind) sT1[tok * 2 + d] = acc + w1_b[d];
        else      g_off[win * 128 + tok * 2 + d] = acc + wi_b[d];
    }
    __syncthreads();

    if (tid < 2) {
        float acc = w2_b[tid];
        for (int f = 0; f < 128; ++f)
            acc = fmaf(sT1[f], w2_w[f * 2 + tid], acc);
        g_oi[win * 2 + tid] = acc;
    }
}

// 64x128 GEMM, 16 warps: row-group g = warp>>1 (8 rows), col-half hs = warp&1.
// Each weight load feeds 8 FMAs (8-row reuse preserved).
__device__ __forceinline__
void gemm_block(const float* __restrict__ in_s, const float* __restrict__ w,
                int wstride, int woff, const float* __restrict__ bias, int boff,
                float* __restrict__ out_s, int g, int hs, int tx)
{
    float acc[8][2] = {};
    const int co = hs * 64 + tx;            // cols co, co+32
    #pragma unroll 4
    for (int ci = 0; ci < 128; ++ci) {
        const float* wr = w + (size_t)ci * wstride + woff + co;
        const float w0 = __ldg(wr), w1 = __ldg(wr + 32);
        const float* ar = in_s + (g * 8) * STR + ci;
        #pragma unroll
        for (int r = 0; r < 8; ++r) {
            const float a = ar[r * STR];
            acc[r][0] = fmaf(a, w0, acc[r][0]);
            acc[r][1] = fmaf(a, w1, acc[r][1]);
        }
    }
    #pragma unroll
    for (int r = 0; r < 8; ++r) {
        out_s[(g * 8 + r) * STR + co]      = acc[r][0] + bias[boff + co];
        out_s[(g * 8 + r) * STR + co + 32] = acc[r][1] + bias[boff + co + 32];
    }
}

// ---------------- kernel 2 ----------------
__global__ __launch_bounds__(NTHR)
void k_main(const float* __restrict__ rpp,
            const float* __restrict__ q_w,  const float* __restrict__ q_b,
            const float* __restrict__ kv_w, const float* __restrict__ kv_b,
            const float* __restrict__ o_w,  const float* __restrict__ o_b,
            float* __restrict__ out)
{
    extern __shared__ float sm[];
    float* sA   = sm;                   // xd -> xw -> k
    float* sB   = sA + P2 * STR;        // xd2 -> attn-out
    float* sC   = sB + P2 * STR;        // q
    float* sD   = sC + P2 * STR;        // v
    float* sSim = sD + P2 * STR;        // 64x64
    float* sW   = sSim + 4096;
    int*   sIdx = (int*)(sW + 256);

    const int win = blockIdx.x;
    const int b   = win >> 10;
    const int wr  = win & 1023;
    const int wi  = wr >> 5;
    const int wj  = wr & 31;
    const int tid = threadIdx.x;
    const int wp  = tid >> 5, tx = tid & 31;
    const int g   = wp >> 1, hs = wp & 1;   // GEMM mapping

    // ---- inter-window bilinear blend -> sA (xd) ----
    {
        const float ox = g_oi[win * 2 + 0], oy = g_oi[win * 2 + 1];
        const float gxp = (float)wj + ox, gyp = (float)wi + oy;
        const float x0f = floorf(gxp), y0f = floorf(gyp);
        const float fx = gxp - x0f, fy = gyp - y0f;
        const int x0 = (int)x0f, y0 = (int)y0f;
        const float wgt[4] = {(1.f - fx) * (1.f - fy), fx * (1.f - fy),
                              (1.f - fx) * fy,          fx * fy};
        const float* nb[4];
        float nww[4];
        #pragma unroll
        for (int k = 0; k < 4; ++k) {
            const int xx = x0 + (k & 1), yy = y0 + (k >> 1);
            const bool valid = (xx >= 0) && (xx < W1G) && (yy >= 0) && (yy < W1G);
            nb[k]  = valid ? (g_xw + (size_t)((b << 10) + (yy << 5) + xx) * P2 * CH) : g_xw;
            nww[k] = valid ? wgt[k] : 0.f;
        }
        for (int idx = tid; idx < P2 * CH; idx += NTHR) {
            const float acc = nww[0] * nb[0][idx] + nww[1] * nb[1][idx]
                            + nww[2] * nb[2][idx] + nww[3] * nb[3][idx];
            sA[(idx >> 7) * STR + (idx & 127)] = acc;
        }
    }
    if (tid < 64) {
        const int tok = tid, pi = tok >> 3, pj = tok & 7;
        const float o0 = g_off[win * 128 + tok * 2], o1 = g_off[win * 128 + tok * 2 + 1];
        const float gx2 = (float)pj + o0, gy2 = (float)pi + o1;
        const float xf = floorf(gx2), yf = floorf(gy2);
        const float fx = gx2 - xf, fy = gy2 - yf;
        const int x0 = (int)xf, y0 = (int)yf;
        const float ww[4] = {(1.f - fx) * (1.f - fy), fx * (1.f - fy),
                             (1.f - fx) * fy,          fx * fy};
        #pragma unroll
        for (int k = 0; k < 4; ++k) {
            const int xx = x0 + (k & 1), yy = y0 + (k >> 1);
            const bool valid = (xx >= 0) && (xx < WSZ) && (yy >= 0) && (yy < WSZ);
            sIdx[tok * 4 + k] = valid ? (yy * 8 + xx) : 0;
            sW[tok * 4 + k]   = valid ? ww[k] : 0.f;
        }
    }
    __syncthreads();

    // ---- intra-window gather -> sB (xd2) ----
    for (int idx = tid; idx < P2 * CH; idx += NTHR) {
        const int tok = idx >> 7, ch = idx & 127;
        float acc = 0.f;
        #pragma unroll
        for (int k = 0; k < 4; ++k)
            acc = fmaf(sW[tok * 4 + k], sA[sIdx[tok * 4 + k] * STR + ch], acc);
        sB[tok * STR + ch] = acc;
    }
    __syncthreads();

    // ---- own window xw -> sA ----
    {
        const float* gx = g_xw + (size_t)win * P2 * CH;
        for (int idx = tid; idx < P2 * CH; idx += NTHR)
            sA[(idx >> 7) * STR + (idx & 127)] = gx[idx];
    }
    __syncthreads();

    // ---- q = xw @ q_w -> sC ----
    gemm_block(sA, q_w, 128, 0, q_b, 0, sC, g, hs, tx);
    __syncthreads();
    // ---- k -> sA ; v -> sD (both from xd2 in sB) ----
    gemm_block(sB, kv_w, 256, 0,   kv_b, 0,   sA, g, hs, tx);
    gemm_block(sB, kv_w, 256, 128, kv_b, 128, sD, g, hs, tx);
    __syncthreads();

    // ---- attention: each warp owns 4 query rows ----
    const float scale = 0.17677669529663687f;
    const bool lastRow = (wi == W1G - 1), lastCol = (wj == W1G - 1);
    const int r0 = wp * 4;
    for (int hh = 0; hh < NH; ++hh) {
        float acc[4][2] = {};
        const float* qb_ = sC + r0 * STR + hh * HD;
        const float* k0p = sA + tx * STR + hh * HD;
        const float* k1p = sA + (tx + 32) * STR + hh * HD;
        #pragma unroll 4
        for (int d = 0; d < HD; ++d) {
            const float kk0 = k0p[d], kk1 = k1p[d];
            #pragma unroll
            for (int r = 0; r < 4; ++r) {
                const float qv = qb_[r * STR + d];
                acc[r][0] = fmaf(qv, kk0, acc[r][0]);
                acc[r][1] = fmaf(qv, kk1, acc[r][1]);
            }
        }
        const float* rb = rpp + hh * 225;
        #pragma unroll
        for (int r = 0; r < 4; ++r) {
            const int i = r0 + r, pi_i = i >> 3, pj_i = i & 7;
            #pragma unroll
            for (int u = 0; u < 2; ++u) {
                const int j = tx + 32 * u, pi_j = j >> 3, pj_j = j & 7;
                const float bias = rb[(pi_i - pi_j + 7) * 15 + (pj_i - pj_j + 7)];
                const bool msk = (lastRow && ((pi_i < 4) != (pi_j < 4)))
                              || (lastCol && ((pj_i < 4) != (pj_j < 4)));
                sSim[i * 64 + j] = msk ? -CUDART_INF_F : fmaf(acc[r][u], scale, bias);
            }
        }
        __syncwarp();
        #pragma unroll
        for (int r = 0; r < 4; ++r) {
            const int i = r0 + r;
            const float a = sSim[i * 64 + tx], bb = sSim[i * 64 + tx + 32];
            float m = fmaxf(a, bb);
            #pragma unroll
            for (int s2 = 16; s2 > 0; s2 >>= 1) m = fmaxf(m, __shfl_xor_sync(0xffffffffu, m, s2));
            const float e0 = __expf(a - m), e1 = __expf(bb - m);
            float s = e0 + e1;
            #pragma unroll
            for (int s2 = 16; s2 > 0; s2 >>= 1) s += __shfl_xor_sync(0xffffffffu, s, s2);
            const float inv = 1.f / s;
            sSim[i * 64 + tx]      = e0 * inv;
            sSim[i * 64 + tx + 32] = e1 * inv;
        }
        __syncwarp();
        float po[4] = {};
        #pragma unroll 4
        for (int j = 0; j < 64; ++j) {
            const float vv = sD[j * STR + hh * HD + tx];
            #pragma unroll
            for (int r = 0; r < 4; ++r)
                po[r] = fmaf(sSim[(r0 + r) * 64 + j], vv, po[r]);
        }
        #pragma unroll
        for (int r = 0; r < 4; ++r)
            sB[(r0 + r) * STR + hh * HD + tx] = po[r];
        __syncwarp();
    }
    __syncthreads();

    // ---- o projection + un-shift scatter ----
    {
        float acc[8][2] = {};
        const int co = hs * 64 + tx;
        #pragma unroll 4
        for (int ci = 0; ci < 128; ++ci) {
            const float* wrp = o_w + ci * 128 + co;
            const float w0 = __ldg(wrp), w1 = __ldg(wrp + 32);
            const float* ar = sB + (g * 8) * STR + ci;
            #pragma unroll
            for (int r = 0; r < 8; ++r) {
                const float a = ar[r * STR];
                acc[r][0] = fmaf(a, w0, acc[r][0]);
                acc[r][1] = fmaf(a, w1, acc[r][1]);
            }
        }
        const float b0 = o_b[co], b1 = o_b[co + 32];
        #pragma unroll
        for (int r = 0; r < 8; ++r) {
            const int tok = g * 8 + r, pi = tok >> 3, pj = tok & 7;
            const int rr = (wi * 8 + pi + SHIFT) & 255;
            const int cc = (wj * 8 + pj + SHIFT) & 255;
            float* op = out + (size_t)((((b << 8) + rr) << 8) + cc) * CH;
            op[co]      = acc[r][0] + b0;
            op[co + 32] = acc[r][1] + b1;
        }
    }
}

extern "C" void kernel_launch(void* const* d_in, const int* in_sizes, int n_in,
                              void* d_out, int out_size)
{
    const float* x    = (const float*)d_in[0];
    const float* rpp  = (const float*)d_in[1];
    const float* wi_w = (const float*)d_in[2];
    const float* wi_b = (const float*)d_in[3];
    const float* w1_w = (const float*)d_in[4];
    const float* w1_b = (const float*)d_in[5];
    const float* w2_w = (const float*)d_in[6];
    const float* w2_b = (const float*)d_in[7];
    const float* q_w  = (const float*)d_in[8];
    const float* q_b  = (const float*)d_in[9];
    const float* kv_w = (const float*)d_in[10];
    const float* kv_b = (const float*)d_in[11];
    const float* o_w  = (const float*)d_in[12];
    const float* o_b  = (const float*)d_in[13];
    float* out = (float*)d_out;

    const size_t smem2 = (size_t)(4 * P2 * STR + 4096 + 256 + 256) * sizeof(float);
    cudaFuncSetAttribute(k_main, cudaFuncAttributeMaxDynamicSharedMemorySize, (int)smem2);

    k_prep<<<NWIN, 256>>>(x, wi_w, wi_b, w1_w, w1_b, w2_w, w2_b);
    k_main<<<NWIN, NTHR, smem2>>>(rpp, q_w, q_b, kv_w, kv_b, o_w, o_b, out);
}